// round 16
// baseline (speedup 1.0000x reference)
#include <cuda_runtime.h>
#include <cstdint>

#define S_  1024
#define B_  64
#define I_  256
#define H_  512
#define NC  128      // persistent CTAs (16 h-groups x 8 b-groups)
#define NHG 16

// ---------------- scratch (static __device__ — no allocation) ----------------
__device__ float  g_A[(size_t)S_ * B_ * H_];      // x @ W_in.T + b_in      [t*64+b][j]
__device__ float  g_C[(size_t)S_ * B_ * H_];      // x @ tau_w1[:,:I].T+b1  [t*64+b][j]
__device__ float  g_f[2][B_][H_];                 // tanh(u) exchange, double-buffered
__device__ float4 g_part4[2][B_][NHG][2];         // 6 partial sums per (b, hgroup)
__device__ unsigned long long g_tickets;          // barrier arrivals (monotonic u64)

// XOR swizzle on a 512-float h row (16B granularity) -> conflict-free LDS.128
__device__ __forceinline__ int hswz(int f) {
    int u = f >> 2;
    u ^= (u >> 3) & 7;
    return (u << 2) | (f & 3);
}
// fast tanh: (1 - e^{-2|x|}) / (1 + e^{-2|x|}), sign-restored (~1e-6 abs err)
__device__ __forceinline__ float tanh_f(float x) {
    float e = __expf(-2.f * fabsf(x));
    float t = __fdividef(1.f - e, 1.f + e);
    return copysignf(t, x);
}
__device__ __forceinline__ unsigned f2tf32(float f) {
    unsigned u;
    asm("cvt.rna.tf32.f32 %0, %1;" : "=r"(u) : "f"(f));
    return u;
}
// paired-k position within a 512/256-wide row: element k -> slot
// (pairs (k, k+4) land adjacent -> one LDS.64 per mma fragment pair)
__device__ __forceinline__ int kpos(int k) {
    return (k >> 3) * 8 + ((k >> 2) & 1) + 2 * (k & 3);
}
__device__ __forceinline__ void mma_tf32(float* acc, unsigned a0, unsigned a2,
                                         unsigned b0, unsigned b1) {
    asm volatile(
        "mma.sync.aligned.m16n8k8.row.col.f32.tf32.tf32.f32 "
        "{%0,%1,%2,%3}, {%4,%5,%6,%7}, {%8,%9}, {%0,%1,%2,%3};"
        : "+f"(acc[0]), "+f"(acc[1]), "+f"(acc[2]), "+f"(acc[3])
        : "r"(a0), "r"(a0), "r"(a2), "r"(a2), "r"(b0), "r"(b1));
}

// =============================================================================
// Kernel 1: time-parallel precompute GEMM on tensor cores (tf32). R15-verified.
// =============================================================================
#define GROW 132
#define GSM  (2 * 128 * GROW * 4)

__global__ __launch_bounds__(256) void precompute_gemm_tf32(
    const float* __restrict__ x, const float* __restrict__ W_in,
    const float* __restrict__ b_in, const float* __restrict__ tau_w1,
    const float* __restrict__ tau_b1)
{
    extern __shared__ __align__(16) unsigned gsm[];
    unsigned* xs = gsm;
    unsigned* ws = gsm + 128 * GROW;

    const int tid   = threadIdx.x;
    const int mtile = blockIdx.x;
    const int nbase = blockIdx.y * 128;
    const int warp  = tid >> 5, lane = tid & 31;
    const int gid   = lane >> 2, tig = lane & 3;
    const int wm    = warp & 3;
    const int wn    = warp >> 2;

    float acc[2][8][4];
    #pragma unroll
    for (int mt = 0; mt < 2; mt++)
        #pragma unroll
        for (int nt = 0; nt < 8; nt++)
            #pragma unroll
            for (int c = 0; c < 4; c++) acc[mt][nt][c] = 0.f;

    const int srow = tid >> 1;
    const int shalf = tid & 1;

    for (int kc = 0; kc < 2; kc++) {
        {
            int r = mtile * 128 + srow;
            int t = r >> 6, b = r & 63;
            const float* src = x + ((size_t)b * S_ + t) * I_ + kc * 128 + shalf * 64;
            unsigned* dst = xs + srow * GROW;
            #pragma unroll
            for (int i = 0; i < 16; i++) {
                int k0 = shalf * 64 + i * 4;
                float4 v = *(const float4*)(src + i * 4);
                int p = (k0 >> 3) * 8 + ((k0 >> 2) & 1);
                dst[p]     = f2tf32(v.x);
                dst[p + 2] = f2tf32(v.y);
                dst[p + 4] = f2tf32(v.z);
                dst[p + 6] = f2tf32(v.w);
            }
        }
        {
            int ng = nbase + srow;
            const float* src = (ng < 512)
                ? (W_in + (size_t)ng * I_)
                : (tau_w1 + (size_t)(ng - 512) * (I_ + H_));
            src += kc * 128 + shalf * 64;
            unsigned* dst = ws + srow * GROW;
            #pragma unroll
            for (int i = 0; i < 16; i++) {
                int k0 = shalf * 64 + i * 4;
                float4 v = *(const float4*)(src + i * 4);
                int p = (k0 >> 3) * 8 + ((k0 >> 2) & 1);
                dst[p]     = f2tf32(v.x);
                dst[p + 2] = f2tf32(v.y);
                dst[p + 4] = f2tf32(v.z);
                dst[p + 6] = f2tf32(v.w);
            }
        }
        __syncthreads();

        #pragma unroll 4
        for (int ks = 0; ks < 16; ks++) {
            int poff = ks * 8 + 2 * tig;
            unsigned a0[2], a1[2], a2[2], a3[2];
            #pragma unroll
            for (int mt = 0; mt < 2; mt++) {
                int row = wm * 32 + mt * 16 + gid;
                uint2 lo = *(const uint2*)(xs + row * GROW + poff);
                uint2 hi = *(const uint2*)(xs + (row + 8) * GROW + poff);
                a0[mt] = lo.x; a2[mt] = lo.y;
                a1[mt] = hi.x; a3[mt] = hi.y;
            }
            #pragma unroll
            for (int nt = 0; nt < 8; nt++) {
                int nrow = wn * 64 + nt * 8 + gid;
                uint2 bq = *(const uint2*)(ws + nrow * GROW + poff);
                #pragma unroll
                for (int mt = 0; mt < 2; mt++) {
                    asm volatile(
                        "mma.sync.aligned.m16n8k8.row.col.f32.tf32.tf32.f32 "
                        "{%0,%1,%2,%3}, {%4,%5,%6,%7}, {%8,%9}, {%0,%1,%2,%3};"
                        : "+f"(acc[mt][nt][0]), "+f"(acc[mt][nt][1]),
                          "+f"(acc[mt][nt][2]), "+f"(acc[mt][nt][3])
                        : "r"(a0[mt]), "r"(a1[mt]), "r"(a2[mt]), "r"(a3[mt]),
                          "r"(bq.x), "r"(bq.y));
                }
            }
        }
        __syncthreads();
    }

    #pragma unroll
    for (int nt = 0; nt < 8; nt++) {
        int ng = nbase + wn * 64 + nt * 8 + 2 * tig;
        float2 bias = (ng < 512) ? *(const float2*)(b_in + ng)
                                 : *(const float2*)(tau_b1 + (ng - 512));
        #pragma unroll
        for (int mt = 0; mt < 2; mt++) {
            int r0 = mtile * 128 + wm * 32 + mt * 16 + gid;
            float2 v0 = make_float2(acc[mt][nt][0] + bias.x,
                                    acc[mt][nt][1] + bias.y);
            float2 v1 = make_float2(acc[mt][nt][2] + bias.x,
                                    acc[mt][nt][3] + bias.y);
            if (ng < 512) {
                *(float2*)(g_A + (size_t)r0 * H_ + ng)       = v0;
                *(float2*)(g_A + (size_t)(r0 + 8) * H_ + ng) = v1;
            } else {
                *(float2*)(g_C + (size_t)r0 * H_ + (ng - 512))       = v0;
                *(float2*)(g_C + (size_t)(r0 + 8) * H_ + (ng - 512)) = v1;
            }
        }
    }
}

// =============================================================================
// Kernel 2: persistent recurrent scan with the GEMV on TENSOR CORES.
//   Per step: D[8 x 64] = h_tf[8 x 512] @ w_tf[64 x 512]^T via m16n8k8 tf32.
//   Warp w in 0..7:  n-tile w,   K-half 0  -> stores partial D to red_s.
//   Warp w in 8..15: n-tile w-8, K-half 1  -> adds, +A/C, tanh -> val_s.
//   Everything after val_s identical to the 5148us champion.
// =============================================================================
// ---------------- dynamic SMEM layout (bytes) ----------------
#define OFF_HS   0                         // h_s   : 8 x 512 f        16384
#define OFF_HTF  16384                     // h_tf  : 512 x 9 u32      18432
#define OFF_WTF  34816                     // w_tf  : 64 x 516 u32     132096
#define OFF_PA   166912                    // pa_s  : 2 x 8 x 32 f     2048
#define OFF_PC   168960                    // pc_s  : 2 x 8 x 32 f     2048
#define OFF_VAL  171008                    // val_s : 8 x 64 f         2048
#define OFF_RED  173056                    // red_s : 8 x 80 f         2560
#define OFF_GAM  175616                    // gam_s : 512 f            2048
#define OFF_BET  177664                    // bet_s : 512 f            2048
#define OFF_ST   179712                    // stats_s: 8 float4        128
#define OFF_W2   179840                    // w2_s  : 32 f             128
#define SSM_TOT  179968

__device__ __forceinline__ void grid_barrier()
{
    __syncthreads();
    if (threadIdx.x == 0) {
        unsigned long long prev;
        asm volatile("atom.release.gpu.add.u64 %0, [%1], %2;"
                     : "=l"(prev) : "l"(&g_tickets), "l"(1ULL) : "memory");
        unsigned long long target = (prev & ~127ULL) + 128ULL;
        unsigned long long cur;
        do {
            asm volatile("ld.acquire.gpu.u64 %0, [%1];"
                         : "=l"(cur) : "l"(&g_tickets) : "memory");
        } while (cur < target);
    }
    __syncthreads();
}

__global__ __launch_bounds__(512, 1) void liquid_recurrent(
    const float* __restrict__ h0,     const float* __restrict__ W_rec,
    const float* __restrict__ tau_w1, const float* __restrict__ tau_w2,
    const float* __restrict__ tau_b2, const float* __restrict__ gamma,
    const float* __restrict__ beta,
    float* __restrict__ out, float* __restrict__ hfin, float* __restrict__ tauh)
{
    extern __shared__ __align__(16) char smem[];
    float*    h_s   = (float*)(smem + OFF_HS);
    unsigned* h_tf  = (unsigned*)(smem + OFF_HTF);
    unsigned* w_tf  = (unsigned*)(smem + OFF_WTF);
    float (*pa_s)[8][32] = (float(*)[8][32])(smem + OFF_PA);
    float (*pc_s)[8][32] = (float(*)[8][32])(smem + OFF_PC);
    float (*val_s)[64]   = (float(*)[64])(smem + OFF_VAL);
    float*    red_s = (float*)(smem + OFF_RED);
    float*    gam_s = (float*)(smem + OFF_GAM);
    float*    bet_s = (float*)(smem + OFF_BET);
    float4*   stats_s = (float4*)(smem + OFF_ST);
    float*    w2_s  = (float*)(smem + OFF_W2);

    const int tid  = threadIdx.x;
    const int hg   = blockIdx.x & 15;
    const int bg   = blockIdx.x >> 4;
    const int warp = tid >> 5, lane = tid & 31;
    const int gid  = lane >> 2, tig = lane & 3;
    const int nt   = warp & 7;              // n-tile (8 outputs)
    const int khalf = warp >> 3;            // K half (0: k<256, 1: k>=256)

    const int sw_tid = hswz(tid);
    const int sw_j   = hswz(hg * 32 + lane);

    gam_s[tid] = gamma[tid];
    bet_s[tid] = beta[tid];
    if (tid < 32) w2_s[tid] = tau_w2[hg * 32 + tid];
    const float tb2 = tau_b2[0];

    // ---- stage recurrent weights (64 rows x 512 k) as tf32, paired-k ----
    {
        int jj = tid >> 3;                  // 0..63
        const float* src = (jj < 32)
            ? (W_rec + (size_t)(hg * 32 + jj) * H_)
            : (tau_w1 + (size_t)(hg * 32 + jj - 32) * (I_ + H_) + I_);
        unsigned* dst = w_tf + jj * 516;
        #pragma unroll
        for (int i = 0; i < 16; i++) {
            int k0 = (tid & 7) * 64 + i * 4;
            float4 v = *(const float4*)(src + k0);
            int p = (k0 >> 3) * 8 + ((k0 >> 2) & 1);
            dst[p]     = f2tf32(v.x);
            dst[p + 2] = f2tf32(v.y);
            dst[p + 4] = f2tf32(v.z);
            dst[p + 6] = f2tf32(v.w);
        }
    }
    // ---- h0 -> h_s (fp32, swizzled) and h_tf (tf32, [k][b]) ----
    #pragma unroll
    for (int b = 0; b < 8; b++) {
        float hv = h0[(size_t)(bg * 8 + b) * H_ + tid];
        h_s[(b << 9) + sw_tid] = hv;
        h_tf[tid * 9 + b] = f2tf32(hv);
    }
    // prologue: A/C tiles for t=0
    {
        int bb = (tid & 255) >> 5, jj = tid & 31;
        size_t base = ((size_t)(bg * 8 + bb)) * H_ + hg * 32 + jj;
        if (tid < 256) pa_s[0][bb][jj] = g_A[base];
        else           pc_s[0][bb][jj] = g_C[base];
    }
    __syncthreads();

    const float gam = gam_s[tid], bet = bet_s[tid];
    const unsigned* wrow = w_tf + (nt * 8 + gid) * 516;

    for (int t = 0; t < S_; t++) {
        const int par = t & 1;

        // prefetch next step's A/C tile into registers (DRAM latency hidden)
        float pf = 0.f;
        const int pt = t + 1;
        const int pbb = (tid & 255) >> 5, pjj = tid & 31;
        if (pt < S_) {
            size_t base = ((size_t)pt * B_ + bg * 8 + pbb) * H_ + hg * 32 + pjj;
            pf = (tid < 256) ? g_A[base] : g_C[base];
        }

        // ---- GEMV on tensor cores: 32 mma per warp (half K, one n-tile) ----
        float acc[4] = {0.f, 0.f, 0.f, 0.f};
        {
            const int kb0 = khalf * 32;
            #pragma unroll 8
            for (int ks = 0; ks < 32; ks++) {
                int kb = kb0 + ks;
                unsigned a0 = h_tf[(kb * 8 + tig) * 9 + gid];
                unsigned a2 = h_tf[(kb * 8 + tig + 4) * 9 + gid];
                uint2 bq = *(const uint2*)(wrow + kb * 8 + 2 * tig);
                mma_tf32(acc, a0, a2, bq.x, bq.y);
            }
        }
        // warps 0-7: store K-half-0 partial D (rows g<8 live in d0,d1)
        if (khalf == 0)
            *(float2*)(red_s + warp * 80 + gid * 10 + 2 * tig) =
                make_float2(acc[0], acc[1]);
        __syncthreads();

        // stash prefetched tile into the other parity buffer
        if (pt < S_) {
            if (tid < 256) pa_s[pt & 1][pbb][pjj] = pf;
            else           pc_s[pt & 1][pbb][pjj] = pf;
        }
        // warps 8-15: merge halves, add A/C, tanh -> val_s
        if (khalf == 1) {
            float2 r2 = *(const float2*)(red_s + nt * 80 + gid * 10 + 2 * tig);
            int c0 = nt * 8 + 2 * tig;      // 0..63 (even); <32 = f, >=32 = t_hid
            float u0 = r2.x + acc[0];
            float u1 = r2.y + acc[1];
            float add0 = (c0 < 32) ? pa_s[par][gid][c0]
                                   : pc_s[par][gid][c0 - 32];
            float add1 = (c0 < 32) ? pa_s[par][gid][c0 + 1]
                                   : pc_s[par][gid][c0 + 1 - 32];
            val_s[gid][c0]     = tanh_f(u0 + add0);
            val_s[gid][c0 + 1] = tanh_f(u1 + add1);
        }
        __syncthreads();

        // publish f slice (coalesced)
        if (tid < 256) {
            int b = tid >> 5, jj = tid & 31;
            g_f[par][bg * 8 + b][hg * 32 + jj] = val_s[b][jj];
        }
        // per-row partial sums over this j-slice (warp b)
        if (warp < 8) {
            int b = warp;
            float f  = val_s[b][lane];
            float th = val_s[b][lane + 32];
            float h  = h_s[(b << 9) + sw_j];
            float p0 = f, p1 = f * f, p2 = h * f;
            float p3 = th * w2_s[lane], p4 = h, p5 = h * h;
            #pragma unroll
            for (int off = 16; off; off >>= 1) {
                p0 += __shfl_down_sync(0xffffffffu, p0, off);
                p1 += __shfl_down_sync(0xffffffffu, p1, off);
                p2 += __shfl_down_sync(0xffffffffu, p2, off);
                p3 += __shfl_down_sync(0xffffffffu, p3, off);
                p4 += __shfl_down_sync(0xffffffffu, p4, off);
                p5 += __shfl_down_sync(0xffffffffu, p5, off);
            }
            if (lane == 0) {
                g_part4[par][bg * 8 + b][hg][0] = make_float4(p0, p1, p2, p3);
                g_part4[par][bg * 8 + b][hg][1] = make_float4(p4, p5, 0.f, 0.f);
            }
        }

        grid_barrier();     // the ONLY grid sync this step

        // ---- hoisted loads: partials first, then all f rows (overlap L2) ----
        float4 u  = make_float4(0.f, 0.f, 0.f, 0.f);
        float4 v4 = make_float4(0.f, 0.f, 0.f, 0.f);
        if (warp < 8 && lane < 16) {
            u  = __ldcg(&g_part4[par][bg * 8 + warp][lane][0]);
            v4 = __ldcg(&g_part4[par][bg * 8 + warp][lane][1]);
        }
        float f_r[8];
        #pragma unroll
        for (int b = 0; b < 8; b++)
            f_r[b] = __ldcg(&g_f[par][bg * 8 + b][tid]);

        // ---- row stats (data in lanes 0-15 -> tree starts at off=8) ----
        if (warp < 8) {
            float s0 = u.x, s1 = u.y, s2 = u.z, s3r = u.w, s4 = v4.x, s5 = v4.y;
            #pragma unroll
            for (int off = 8; off; off >>= 1) {
                s0  += __shfl_down_sync(0xffffffffu, s0, off);
                s1  += __shfl_down_sync(0xffffffffu, s1, off);
                s2  += __shfl_down_sync(0xffffffffu, s2, off);
                s3r += __shfl_down_sync(0xffffffffu, s3r, off);
                s4  += __shfl_down_sync(0xffffffffu, s4, off);
                s5  += __shfl_down_sync(0xffffffffu, s5, off);
            }
            if (lane == 0) {
                int bG = bg * 8 + warp;
                float tau  = 1.f + 9.f / (1.f + __expf(-(s3r + tb2)));
                float cc   = 0.1f / tau;
                float aa   = 1.f - cc;
                float mean = (aa * s4 + cc * s0) * (1.f / 512.f);
                float ep2  = (aa * aa * s5 + 2.f * aa * cc * s2 + cc * cc * s1)
                             * (1.f / 512.f);
                float rstd = rsqrtf(ep2 - mean * mean + 1e-5f);
                stats_s[warp] = make_float4(aa, cc, mean, rstd);
                if (hg == 0) tauh[(size_t)bG * S_ + t] = tau;
            }
        }
        __syncthreads();

        // ---- reconstruct full h_new rows; refresh h_s + h_tf ----
        #pragma unroll
        for (int b = 0; b < 8; b++) {
            float4 st = stats_s[b];
            float h = h_s[(b << 9) + sw_tid];
            float p  = st.x * h + st.y * f_r[b];
            float hn = (p - st.z) * st.w * gam + bet;
            h_s[(b << 9) + sw_tid] = hn;
            h_tf[tid * 9 + b] = f2tf32(hn);
            if ((tid >> 5) == hg) {
                out[((size_t)(bg * 8 + b) * S_ + t) * H_ + tid] = hn;
                if (t == S_ - 1) hfin[(size_t)(bg * 8 + b) * H_ + tid] = hn;
            }
        }
        __syncthreads();   // h_s/h_tf reuse ordering for next step
    }
}

// =============================================================================
extern "C" void kernel_launch(void* const* d_in, const int* in_sizes, int n_in,
                              void* d_out, int out_size)
{
    const float* x     = (const float*)d_in[0];
    const float* h0    = (const float*)d_in[1];
    const float* W_in  = (const float*)d_in[2];
    const float* b_in  = (const float*)d_in[3];
    const float* W_rec = (const float*)d_in[4];
    const float* tw1   = (const float*)d_in[5];
    const float* tb1   = (const float*)d_in[6];
    const float* tw2   = (const float*)d_in[7];
    const float* tb2   = (const float*)d_in[8];
    const float* gamma = (const float*)d_in[9];
    const float* beta  = (const float*)d_in[10];

    float* out  = (float*)d_out;                       // [B, S, H]
    float* hfin = out + (size_t)B_ * S_ * H_;          // [B, H]
    float* tauh = hfin + (size_t)B_ * H_;              // [B, S, 1]

    cudaFuncSetAttribute(precompute_gemm_tf32,
                         cudaFuncAttributeMaxDynamicSharedMemorySize, GSM);
    cudaFuncSetAttribute(liquid_recurrent,
                         cudaFuncAttributeMaxDynamicSharedMemorySize, SSM_TOT);
    precompute_gemm_tf32<<<dim3(512, 8), 256, GSM>>>(x, W_in, b_in, tw1, tb1);
    liquid_recurrent<<<NC, 512, SSM_TOT>>>(h0, W_rec, tw1, tw2, tb2, gamma,
                                           beta, out, hfin, tauh);
}

// round 17
// speedup vs baseline: 1.1431x; 1.1431x over previous
#include <cuda_runtime.h>
#include <cstdint>

#define S_  1024
#define B_  64
#define I_  256
#define H_  512
#define NC  128      // persistent CTAs (16 h-groups x 8 b-groups)
#define NHG 16

// ---------------- scratch (static __device__ — no allocation) ----------------
__device__ float  g_A[(size_t)S_ * B_ * H_];      // x @ W_in.T + b_in      [t*64+b][j]
__device__ float  g_C[(size_t)S_ * B_ * H_];      // x @ tau_w1[:,:I].T+b1  [t*64+b][j]
__device__ float  g_f[2][B_][H_];                 // tanh(u) exchange, double-buffered
__device__ float4 g_part4[2][B_][NHG][2];         // 6 partial sums per (b, hgroup)
__device__ unsigned long long g_tickets;          // barrier arrivals (monotonic u64)

// ---- packed fp32x2 helpers (Blackwell dual-issue fp32) ----
#define FMA2(d, a, b) \
    asm("fma.rn.f32x2 %0, %1, %2, %0;" : "+l"(d) : "l"(a), "l"(b))

__device__ __forceinline__ unsigned long long pk2(float a, float b) {
    return (unsigned long long)__float_as_uint(a) |
           ((unsigned long long)__float_as_uint(b) << 32);
}
__device__ __forceinline__ float fold2(unsigned long long v) {
    return __uint_as_float((unsigned)v) + __uint_as_float((unsigned)(v >> 32));
}
// XOR swizzle on a 512-float h row (16B granularity) -> conflict-free LDS.128
__device__ __forceinline__ int hswz(int f) {
    int u = f >> 2;
    u ^= (u >> 3) & 7;
    return (u << 2) | (f & 3);
}
// fast tanh: (1 - e^{-2|x|}) / (1 + e^{-2|x|}), sign-restored (~1e-6 abs err)
__device__ __forceinline__ float tanh_f(float x) {
    float e = __expf(-2.f * fabsf(x));
    float t = __fdividef(1.f - e, 1.f + e);
    return copysignf(t, x);
}
__device__ __forceinline__ unsigned f2tf32(float f) {
    unsigned u;
    asm("cvt.rna.tf32.f32 %0, %1;" : "=r"(u) : "f"(f));
    return u;
}

// =============================================================================
// Kernel 1: time-parallel precompute GEMM on tensor cores (tf32).
//   R15-verified fragment/slot layout; NEW: vectorized paired staging
//   (2x STS.128 per 8 elems) and K-chunk=64 -> 70KB SMEM -> 2-3 CTAs/SM.
// =============================================================================
#define GROW2 68                              // 64 slots + 4 pad (words)
#define GSM   (2 * 128 * GROW2 * 4)           // xs + ws = 69632 B

__global__ __launch_bounds__(256, 2) void precompute_gemm_tf32(
    const float* __restrict__ x, const float* __restrict__ W_in,
    const float* __restrict__ b_in, const float* __restrict__ tau_w1,
    const float* __restrict__ tau_b1)
{
    extern __shared__ __align__(16) unsigned gsm[];
    unsigned* xs = gsm;                       // [128][GROW2]
    unsigned* ws = gsm + 128 * GROW2;         // [128][GROW2]

    const int tid   = threadIdx.x;
    const int mtile = blockIdx.x;             // 0..511 (128 r each)
    const int nbase = blockIdx.y * 128;       // 0..896
    const int warp  = tid >> 5, lane = tid & 31;
    const int gid   = lane >> 2, tig = lane & 3;
    const int wm    = warp & 3;               // m-quadrant (32 rows)
    const int wn    = warp >> 2;              // n-half (64 cols)

    float acc[2][8][4];
    #pragma unroll
    for (int mt = 0; mt < 2; mt++)
        #pragma unroll
        for (int nt = 0; nt < 8; nt++)
            #pragma unroll
            for (int c = 0; c < 4; c++) acc[mt][nt][c] = 0.f;

    const int srow  = tid >> 1;               // staging row 0..127
    const int shalf = tid & 1;                // k-half of the 64-chunk

    // global row pointers (hoisted)
    const int r  = mtile * 128 + srow;
    const int tt = r >> 6, bb = r & 63;
    const float* xrow = x + ((size_t)bb * S_ + tt) * I_;
    const int ng = nbase + srow;
    const float* wrow_g = (ng < 512)
        ? (W_in + (size_t)ng * I_)
        : (tau_w1 + (size_t)(ng - 512) * (I_ + H_));

    for (int kc = 0; kc < 4; kc++) {          // 4 chunks of K=64
        // ---- stage x chunk: 4 groups of 8 k -> 2 LDG.128 + 2 STS.128 each --
        {
            const float* src = xrow + kc * 64 + shalf * 32;
            unsigned* dst = xs + srow * GROW2 + shalf * 32;
            #pragma unroll
            for (int g = 0; g < 4; g++) {
                float4 v0 = *(const float4*)(src + g * 8);
                float4 v1 = *(const float4*)(src + g * 8 + 4);
                uint4 s0 = make_uint4(f2tf32(v0.x), f2tf32(v1.x),
                                      f2tf32(v0.y), f2tf32(v1.y));
                uint4 s1 = make_uint4(f2tf32(v0.z), f2tf32(v1.z),
                                      f2tf32(v0.w), f2tf32(v1.w));
                *(uint4*)(dst + g * 8)     = s0;
                *(uint4*)(dst + g * 8 + 4) = s1;
            }
        }
        // ---- stage w chunk (identical pattern) ----
        {
            const float* src = wrow_g + kc * 64 + shalf * 32;
            unsigned* dst = ws + srow * GROW2 + shalf * 32;
            #pragma unroll
            for (int g = 0; g < 4; g++) {
                float4 v0 = *(const float4*)(src + g * 8);
                float4 v1 = *(const float4*)(src + g * 8 + 4);
                uint4 s0 = make_uint4(f2tf32(v0.x), f2tf32(v1.x),
                                      f2tf32(v0.y), f2tf32(v1.y));
                uint4 s1 = make_uint4(f2tf32(v0.z), f2tf32(v1.z),
                                      f2tf32(v0.w), f2tf32(v1.w));
                *(uint4*)(dst + g * 8)     = s0;
                *(uint4*)(dst + g * 8 + 4) = s1;
            }
        }
        __syncthreads();

        // ---- mma main loop: 8 k8-steps in this chunk ----
        #pragma unroll
        for (int ks = 0; ks < 8; ks++) {
            int poff = ks * 8 + 2 * tig;
            unsigned a0[2], a1[2], a2[2], a3[2];
            #pragma unroll
            for (int mt = 0; mt < 2; mt++) {
                int row = wm * 32 + mt * 16 + gid;
                uint2 lo = *(const uint2*)(xs + row * GROW2 + poff);
                uint2 hi = *(const uint2*)(xs + (row + 8) * GROW2 + poff);
                a0[mt] = lo.x; a2[mt] = lo.y;   // (g,tig), (g,tig+4)
                a1[mt] = hi.x; a3[mt] = hi.y;   // (g+8,tig), (g+8,tig+4)
            }
            #pragma unroll
            for (int nt = 0; nt < 8; nt++) {
                int nrow = wn * 64 + nt * 8 + gid;
                uint2 bq = *(const uint2*)(ws + nrow * GROW2 + poff);
                #pragma unroll
                for (int mt = 0; mt < 2; mt++) {
                    asm volatile(
                        "mma.sync.aligned.m16n8k8.row.col.f32.tf32.tf32.f32 "
                        "{%0,%1,%2,%3}, {%4,%5,%6,%7}, {%8,%9}, {%0,%1,%2,%3};"
                        : "+f"(acc[mt][nt][0]), "+f"(acc[mt][nt][1]),
                          "+f"(acc[mt][nt][2]), "+f"(acc[mt][nt][3])
                        : "r"(a0[mt]), "r"(a1[mt]), "r"(a2[mt]), "r"(a3[mt]),
                          "r"(bq.x), "r"(bq.y));
                }
            }
        }
        __syncthreads();
    }

    // ---- epilogue: add bias, route to g_A / g_C (R15-verified mapping) ----
    #pragma unroll
    for (int nt = 0; nt < 8; nt++) {
        int ngc = nbase + wn * 64 + nt * 8 + 2 * tig;       // even
        float2 bias = (ngc < 512) ? *(const float2*)(b_in + ngc)
                                  : *(const float2*)(tau_b1 + (ngc - 512));
        #pragma unroll
        for (int mt = 0; mt < 2; mt++) {
            int r0 = mtile * 128 + wm * 32 + mt * 16 + gid;
            float2 v0 = make_float2(acc[mt][nt][0] + bias.x,
                                    acc[mt][nt][1] + bias.y);
            float2 v1 = make_float2(acc[mt][nt][2] + bias.x,
                                    acc[mt][nt][3] + bias.y);
            if (ngc < 512) {
                *(float2*)(g_A + (size_t)r0 * H_ + ngc)       = v0;
                *(float2*)(g_A + (size_t)(r0 + 8) * H_ + ngc) = v1;
            } else {
                *(float2*)(g_C + (size_t)r0 * H_ + (ngc - 512))       = v0;
                *(float2*)(g_C + (size_t)(r0 + 8) * H_ + (ngc - 512)) = v1;
            }
        }
    }
}

// =============================================================================
// Kernel 2: persistent recurrent scan — EXACT R15 champion (4.537us/step).
// =============================================================================
__device__ __forceinline__ void grid_barrier()
{
    __syncthreads();
    if (threadIdx.x == 0) {
        unsigned long long prev;
        asm volatile("atom.release.gpu.add.u64 %0, [%1], %2;"
                     : "=l"(prev) : "l"(&g_tickets), "l"(1ULL) : "memory");
        unsigned long long target = (prev & ~127ULL) + 128ULL;
        unsigned long long cur;
        do {
            asm volatile("ld.acquire.gpu.u64 %0, [%1];"
                         : "=l"(cur) : "l"(&g_tickets) : "memory");
        } while (cur < target);
    }
    __syncthreads();
}

__global__ __launch_bounds__(512, 1) void liquid_recurrent(
    const float* __restrict__ h0,     const float* __restrict__ W_rec,
    const float* __restrict__ tau_w1, const float* __restrict__ tau_w2,
    const float* __restrict__ tau_b2, const float* __restrict__ gamma,
    const float* __restrict__ beta,
    float* __restrict__ out, float* __restrict__ hfin, float* __restrict__ tauh)
{
    __shared__ __align__(16) float h_s[8 * H_];     // swizzled h rows (16 KB)
    __shared__ float  pa_s[2][8][32];               // A tiles, double-buffered
    __shared__ float  pc_s[2][8][32];               // C tiles, double-buffered
    __shared__ float  val_s[8][64];                 // f (o<32) / t_hid (o>=32)
    __shared__ float4 stats_s[8];                   // {a, c, mean, rstd}
    __shared__ float  gam_s[H_], bet_s[H_];
    __shared__ float  w2_s[32];

    const int tid  = threadIdx.x;
    const int hg   = blockIdx.x & 15;
    const int bg   = blockIdx.x >> 4;
    const int warp = tid >> 5, lane = tid & 31;
    const bool is_rec = (warp < 8);
    const int jlb  = (warp & 7) * 4;                // jl base for this warp

    // ---- recurrent weights -> registers as f32x2 k-pairs (64 regs) ----
    unsigned long long w2r[32];
    {
        #pragma unroll
        for (int op = 0; op < 4; op++) {
            int j = hg * 32 + jlb + op;
            const float* wr = is_rec ? (W_rec + (size_t)j * H_)
                                     : (tau_w1 + (size_t)j * (I_ + H_) + I_);
            #pragma unroll
            for (int p4 = 0; p4 < 4; p4++) {
                float4 v = *(const float4*)(wr + lane * 16 + p4 * 4);
                w2r[op * 8 + p4 * 2]     = pk2(v.x, v.y);
                w2r[op * 8 + p4 * 2 + 1] = pk2(v.z, v.w);
            }
        }
    }
    const int s3 = (lane >> 1) & 7;
    int hoff[4];
    #pragma unroll
    for (int p4 = 0; p4 < 4; p4++) hoff[p4] = ((lane * 4 + p4) ^ s3) << 2;
    const int sw_tid = hswz(tid);
    const int sw_j   = hswz(hg * 32 + lane);

    gam_s[tid] = gamma[tid];
    bet_s[tid] = beta[tid];
    if (tid < 32) w2_s[tid] = tau_w2[hg * 32 + tid];
    const float tb2 = tau_b2[0];
    #pragma unroll
    for (int b = 0; b < 8; b++)
        h_s[(b << 9) + sw_tid] = h0[(size_t)(bg * 8 + b) * H_ + tid];
    // prologue: tiles for t=0
    {
        int bb = (tid & 255) >> 5, jj = tid & 31;
        size_t base = ((size_t)(bg * 8 + bb)) * H_ + hg * 32 + jj;
        if (tid < 256) pa_s[0][bb][jj] = g_A[base];
        else           pc_s[0][bb][jj] = g_C[base];
    }
    __syncthreads();

    const float gam = gam_s[tid], bet = bet_s[tid];

    for (int t = 0; t < S_; t++) {
        const int par = t & 1;

        // prefetch next step's A/C tile into registers (DRAM latency hidden)
        float pf = 0.f;
        const int pt = t + 1;
        const int pbb = (tid & 255) >> 5, pjj = tid & 31;
        if (pt < S_) {
            size_t base = ((size_t)pt * B_ + bg * 8 + pbb) * H_ + hg * 32 + pjj;
            pf = (tid < 256) ? g_A[base] : g_C[base];
        }

        // ---- GEMV: 4 outputs/warp, 16 k per lane, fp32x2 ----
        #pragma unroll
        for (int hb = 0; hb < 2; hb++) {
            unsigned long long acc2[16];
            #pragma unroll
            for (int i = 0; i < 16; i++) acc2[i] = 0ULL;
            #pragma unroll
            for (int b4 = 0; b4 < 4; b4++) {
                const float* hp = h_s + ((hb * 4 + b4) << 9);
                #pragma unroll
                for (int p4 = 0; p4 < 4; p4++) {
                    ulonglong2 hv = *(const ulonglong2*)(hp + hoff[p4]);
                    #pragma unroll
                    for (int op = 0; op < 4; op++) {
                        FMA2(acc2[op * 4 + b4], hv.x, w2r[op * 8 + p4 * 2]);
                        FMA2(acc2[op * 4 + b4], hv.y, w2r[op * 8 + p4 * 2 + 1]);
                    }
                }
            }
            // fold k-pairs, butterfly-reduce 16 values over 32 lanes
            float r[16];
            #pragma unroll
            for (int i = 0; i < 16; i++) r[i] = fold2(acc2[i]);
            {
                int up = lane & 16;
                #pragma unroll
                for (int i = 0; i < 8; i++) {
                    float snd = up ? r[i] : r[i + 8];
                    float kp  = up ? r[i + 8] : r[i];
                    r[i] = kp + __shfl_xor_sync(0xffffffffu, snd, 16);
                }
                up = lane & 8;
                #pragma unroll
                for (int i = 0; i < 4; i++) {
                    float snd = up ? r[i] : r[i + 4];
                    float kp  = up ? r[i + 4] : r[i];
                    r[i] = kp + __shfl_xor_sync(0xffffffffu, snd, 8);
                }
                up = lane & 4;
                #pragma unroll
                for (int i = 0; i < 2; i++) {
                    float snd = up ? r[i] : r[i + 2];
                    float kp  = up ? r[i + 2] : r[i];
                    r[i] = kp + __shfl_xor_sync(0xffffffffu, snd, 4);
                }
                {
                    int u2 = lane & 2;
                    float snd = u2 ? r[0] : r[1];
                    float kp  = u2 ? r[1] : r[0];
                    r[0] = kp + __shfl_xor_sync(0xffffffffu, snd, 2);
                }
                r[0] += __shfl_xor_sync(0xffffffffu, r[0], 1);
            }
            if (!(lane & 1)) {
                int idx = (lane >> 1) & 15;
                int op = idx >> 2, b4 = idx & 3;
                int b = hb * 4 + b4, jl = jlb + op;
                float add = is_rec ? pa_s[par][b][jl] : pc_s[par][b][jl];
                val_s[b][(is_rec ? 0 : 32) + jl] = tanh_f(r[0] + add);
            }
        }
        __syncthreads();

        // stash prefetched tile into the other buffer
        if (pt < S_) {
            if (tid < 256) pa_s[pt & 1][pbb][pjj] = pf;
            else           pc_s[pt & 1][pbb][pjj] = pf;
        }

        // publish f slice (coalesced)
        if (tid < 256) {
            int b = tid >> 5, jj = tid & 31;
            g_f[par][bg * 8 + b][hg * 32 + jj] = val_s[b][jj];
        }
        // per-row partial sums over this j-slice (warp b)
        if (warp < 8) {
            int b = warp;
            float f  = val_s[b][lane];
            float th = val_s[b][lane + 32];
            float h  = h_s[(b << 9) + sw_j];
            float p0 = f, p1 = f * f, p2 = h * f;
            float p3 = th * w2_s[lane], p4 = h, p5 = h * h;
            #pragma unroll
            for (int off = 16; off; off >>= 1) {
                p0 += __shfl_down_sync(0xffffffffu, p0, off);
                p1 += __shfl_down_sync(0xffffffffu, p1, off);
                p2 += __shfl_down_sync(0xffffffffu, p2, off);
                p3 += __shfl_down_sync(0xffffffffu, p3, off);
                p4 += __shfl_down_sync(0xffffffffu, p4, off);
                p5 += __shfl_down_sync(0xffffffffu, p5, off);
            }
            if (lane == 0) {
                g_part4[par][bg * 8 + b][hg][0] = make_float4(p0, p1, p2, p3);
                g_part4[par][bg * 8 + b][hg][1] = make_float4(p4, p5, 0.f, 0.f);
            }
        }

        grid_barrier();     // the ONLY grid sync this step

        // ---- hoisted loads: partials first, then all f rows (overlap L2) ----
        float4 u  = make_float4(0.f, 0.f, 0.f, 0.f);
        float4 v4 = make_float4(0.f, 0.f, 0.f, 0.f);
        if (warp < 8 && lane < 16) {
            u  = __ldcg(&g_part4[par][bg * 8 + warp][lane][0]);
            v4 = __ldcg(&g_part4[par][bg * 8 + warp][lane][1]);
        }
        float f_r[8];
        #pragma unroll
        for (int b = 0; b < 8; b++)
            f_r[b] = __ldcg(&g_f[par][bg * 8 + b][tid]);

        // ---- row stats (data in lanes 0-15 -> tree starts at off=8) ----
        if (warp < 8) {
            float s0 = u.x, s1 = u.y, s2 = u.z, s3r = u.w, s4 = v4.x, s5 = v4.y;
            #pragma unroll
            for (int off = 8; off; off >>= 1) {
                s0  += __shfl_down_sync(0xffffffffu, s0, off);
                s1  += __shfl_down_sync(0xffffffffu, s1, off);
                s2  += __shfl_down_sync(0xffffffffu, s2, off);
                s3r += __shfl_down_sync(0xffffffffu, s3r, off);
                s4  += __shfl_down_sync(0xffffffffu, s4, off);
                s5  += __shfl_down_sync(0xffffffffu, s5, off);
            }
            if (lane == 0) {
                int bG = bg * 8 + warp;
                float tau  = 1.f + 9.f / (1.f + __expf(-(s3r + tb2)));
                float cc   = 0.1f / tau;
                float aa   = 1.f - cc;
                float mean = (aa * s4 + cc * s0) * (1.f / 512.f);
                float ep2  = (aa * aa * s5 + 2.f * aa * cc * s2 + cc * cc * s1)
                             * (1.f / 512.f);
                float rstd = rsqrtf(ep2 - mean * mean + 1e-5f);
                stats_s[warp] = make_float4(aa, cc, mean, rstd);
                if (hg == 0) tauh[(size_t)bG * S_ + t] = tau;
            }
        }
        __syncthreads();

        // ---- reconstruct full h_new rows; write own output slice ----
        #pragma unroll
        for (int b = 0; b < 8; b++) {
            float4 st = stats_s[b];
            float h = h_s[(b << 9) + sw_tid];
            float p  = st.x * h + st.y * f_r[b];
            float hn = (p - st.z) * st.w * gam + bet;
            h_s[(b << 9) + sw_tid] = hn;
            if ((tid >> 5) == hg) {
                out[((size_t)(bg * 8 + b) * S_ + t) * H_ + tid] = hn;
                if (t == S_ - 1) hfin[(size_t)(bg * 8 + b) * H_ + tid] = hn;
            }
        }
        __syncthreads();   // h_s reuse ordering for next step
    }
}

// =============================================================================
extern "C" void kernel_launch(void* const* d_in, const int* in_sizes, int n_in,
                              void* d_out, int out_size)
{
    const float* x     = (const float*)d_in[0];
    const float* h0    = (const float*)d_in[1];
    const float* W_in  = (const float*)d_in[2];
    const float* b_in  = (const float*)d_in[3];
    const float* W_rec = (const float*)d_in[4];
    const float* tw1   = (const float*)d_in[5];
    const float* tb1   = (const float*)d_in[6];
    const float* tw2   = (const float*)d_in[7];
    const float* tb2   = (const float*)d_in[8];
    const float* gamma = (const float*)d_in[9];
    const float* beta  = (const float*)d_in[10];

    float* out  = (float*)d_out;                       // [B, S, H]
    float* hfin = out + (size_t)B_ * S_ * H_;          // [B, H]
    float* tauh = hfin + (size_t)B_ * H_;              // [B, S, 1]

    cudaFuncSetAttribute(precompute_gemm_tf32,
                         cudaFuncAttributeMaxDynamicSharedMemorySize, GSM);
    precompute_gemm_tf32<<<dim3(512, 8), 256, GSM>>>(x, W_in, b_in, tw1, tb1);
    liquid_recurrent<<<NC, 512>>>(h0, W_rec, tw1, tw2, tb2, gamma, beta,
                                  out, hfin, tauh);
}